// round 15
// baseline (speedup 1.0000x reference)
#include <cuda_runtime.h>
#include <cstddef>

#define Bx 16
#define Lx 4096
#define Dx 1024
#define NSPLIT 64
#define ROWS_PER_SPLIT (Lx / NSPLIT)   // 64
#define SROWS 16                       // rows per score block (8 warps x 2) — R8-proven

// ---- scratch (__device__ globals; no allocation allowed) ----
__device__ float g_df[Bx * Dx];               // dec_feature
__device__ float g_score[Bx * Lx];            // pre-softmax scores
__device__ float g_partial[Bx * NSPLIT * Dx]; // context partials

// d_out layout (float32): attn, context, new_coverage
#define ATTN_OFF 0
#define CTX_OFF  (Bx * Lx)
#define COV_OFF  (Bx * Lx + Bx * Dx)

__device__ __forceinline__ float tanh_approx(float x) {
    float y;
    asm("tanh.approx.f32 %0, %1;" : "=f"(y) : "f"(x));
    return y;
}

// ============================================================
// Kernel 1: dec_feature. grid (Dx, 2): block = one d, 8 batches.
// bias load hoisted off the tail critical path.
// ============================================================
__global__ void k_decfeat(const float* __restrict__ dh,
                          const float* __restrict__ W,
                          const float* __restrict__ bias) {
    int d  = blockIdx.x;
    int bh = blockIdx.y;               // batch half: b in [8*bh, 8*bh+8)
    int t = threadIdx.x, warp = t >> 5, lane = t & 31;

    float bs = (t < 8) ? bias[d] : 0.f;   // overlaps the FMA chain below
    float4 w4 = ((const float4*)(W + (size_t)d * Dx))[t];

    float acc[8];
#pragma unroll
    for (int i = 0; i < 8; i++) {
        float4 h4 = ((const float4*)(dh + (size_t)(bh * 8 + i) * Dx))[t];
        acc[i] = w4.x * h4.x + w4.y * h4.y + w4.z * h4.z + w4.w * h4.w;
    }

    bool hi = (lane & 16) != 0;
#pragma unroll
    for (int i = 0; i < 4; i++) {
        float send = hi ? acc[i] : acc[i + 4];
        float r = __shfl_xor_sync(0xffffffffu, send, 16);
        acc[i] = (hi ? acc[i + 4] : acc[i]) + r;
    }
    bool h2 = (lane & 8) != 0;
#pragma unroll
    for (int i = 0; i < 2; i++) {
        float send = h2 ? acc[i] : acc[i + 2];
        float r = __shfl_xor_sync(0xffffffffu, send, 8);
        acc[i] = (h2 ? acc[i + 2] : acc[i]) + r;
    }
    bool h3 = (lane & 4) != 0;
    {
        float send = h3 ? acc[0] : acc[1];
        float r = __shfl_xor_sync(0xffffffffu, send, 4);
        acc[0] = (h3 ? acc[1] : acc[0]) + r;
    }
    acc[0] += __shfl_xor_sync(0xffffffffu, acc[0], 2);
    acc[0] += __shfl_xor_sync(0xffffffffu, acc[0], 1);

    __shared__ float s[8][8];
    if ((lane & 3) == 0) s[warp][(lane >> 2) & 7] = acc[0];
    __syncthreads();
    if (t < 8) {
        float v = bs;
#pragma unroll
        for (int w = 0; w < 8; w++) v += s[w][t];
        g_df[(bh * 8 + t) * Dx + d] = v;
    }
}

// ============================================================
// Kernel 2: score. Block = 16 rows; warp = 2 rows interleaved
// (w and w+8). ONE pass per warp; cov loads hoisted above barrier.
// (R14-proven)
// ============================================================
__global__ void k_score(const float* __restrict__ ef,
                        const float* __restrict__ cov,
                        const float* __restrict__ wscore,
                        const float* __restrict__ wcov) {
    int b  = blockIdx.y;
    int l0 = blockIdx.x * SROWS;
    int t  = threadIdx.x;
    int warp = t >> 5, lane = t & 31;

    int lA = l0 + warp;
    int lB = lA + 8;
    float cA = cov[b * Lx + lA];          // before barrier: overlaps smem fill
    float cB = cov[b * Lx + lB];
    const float4* rowA = (const float4*)(ef + ((size_t)b * Lx + lA) * Dx);
    const float4* rowB = (const float4*)(ef + ((size_t)b * Lx + lB) * Dx);

    __shared__ float4 s_df[Dx / 4], s_ws[Dx / 4], s_wc[Dx / 4];
    s_df[t] = ((const float4*)(g_df + (size_t)b * Dx))[t];
    s_ws[t] = ((const float4*)wscore)[t];
    s_wc[t] = ((const float4*)wcov)[t];
    __syncthreads();

    float sumA = 0.f, sumB = 0.f;
#pragma unroll
    for (int j = 0; j < 8; j++) {
        int idx = lane + j * 32;
        float4 eA = __ldcs(&rowA[idx]);
        float4 eB = __ldcs(&rowB[idx]);
        float4 dv = s_df[idx];
        float4 wc = s_wc[idx];
        float4 ws = s_ws[idx];
        sumA += tanh_approx(fmaf(cA, wc.x, eA.x + dv.x)) * ws.x
              + tanh_approx(fmaf(cA, wc.y, eA.y + dv.y)) * ws.y
              + tanh_approx(fmaf(cA, wc.z, eA.z + dv.z)) * ws.z
              + tanh_approx(fmaf(cA, wc.w, eA.w + dv.w)) * ws.w;
        sumB += tanh_approx(fmaf(cB, wc.x, eB.x + dv.x)) * ws.x
              + tanh_approx(fmaf(cB, wc.y, eB.y + dv.y)) * ws.y
              + tanh_approx(fmaf(cB, wc.z, eB.z + dv.z)) * ws.z
              + tanh_approx(fmaf(cB, wc.w, eB.w + dv.w)) * ws.w;
    }
#pragma unroll
    for (int off = 16; off; off >>= 1) {
        sumA += __shfl_down_sync(0xffffffffu, sumA, off);
        sumB += __shfl_down_sync(0xffffffffu, sumB, off);
    }
    if (lane == 0) {
        g_score[b * Lx + lA] = sumA;
        g_score[b * Lx + lB] = sumB;
    }
}

// ============================================================
// Kernel 3: masked softmax + renormalize -> attn & new_coverage.
// 512 threads x 8 elems: half the warps in the block reductions.
// softmax -> *mask -> /sum collapses to e*m / sum(e*m).
// ============================================================
__global__ void k_softmax(const float* __restrict__ mask,
                          const float* __restrict__ cov,
                          float* __restrict__ out) {
    int b = blockIdx.x;
    int t = threadIdx.x;                  // 0..511
    int warp = t >> 5, lane = t & 31;     // 16 warps
    __shared__ float red[16];
    __shared__ float bcast;

    const float4* sc = (const float4*)(g_score + (size_t)b * Lx);
    float4 s[2];
    s[0] = sc[t];
    s[1] = sc[t + 512];

    float mx = -1e30f;
#pragma unroll
    for (int i = 0; i < 2; i++)
        mx = fmaxf(mx, fmaxf(fmaxf(s[i].x, s[i].y), fmaxf(s[i].z, s[i].w)));
#pragma unroll
    for (int off = 16; off; off >>= 1)
        mx = fmaxf(mx, __shfl_xor_sync(0xffffffffu, mx, off));
    if (lane == 0) red[warp] = mx;
    __syncthreads();
    if (t < 16) {
        float v = red[t];
#pragma unroll
        for (int off = 8; off; off >>= 1)
            v = fmaxf(v, __shfl_xor_sync(0x0000ffffu, v, off));
        if (t == 0) bcast = v;
    }
    __syncthreads();
    mx = bcast;

    const float4* mkp = (const float4*)(mask + (size_t)b * Lx);
    float4 em[2];
    float lsum = 0.f;
#pragma unroll
    for (int i = 0; i < 2; i++) {
        float4 m4 = mkp[t + i * 512];
        em[i].x = expf(s[i].x - mx) * m4.x;
        em[i].y = expf(s[i].y - mx) * m4.y;
        em[i].z = expf(s[i].z - mx) * m4.z;
        em[i].w = expf(s[i].w - mx) * m4.w;
        lsum += em[i].x + em[i].y + em[i].z + em[i].w;
    }
#pragma unroll
    for (int off = 16; off; off >>= 1)
        lsum += __shfl_xor_sync(0xffffffffu, lsum, off);
    __syncthreads();
    if (lane == 0) red[warp] = lsum;
    __syncthreads();
    if (t < 16) {
        float v = red[t];
#pragma unroll
        for (int off = 8; off; off >>= 1)
            v += __shfl_xor_sync(0x0000ffffu, v, off);
        if (t == 0) bcast = v;
    }
    __syncthreads();
    float inv = 1.f / bcast;

    const float4* cvp = (const float4*)(cov + (size_t)b * Lx);
    float4* attnp = (float4*)(out + ATTN_OFF + (size_t)b * Lx);
    float4* covp  = (float4*)(out + COV_OFF  + (size_t)b * Lx);
#pragma unroll
    for (int i = 0; i < 2; i++) {
        int idx = t + i * 512;
        float4 c4 = cvp[idx];
        float4 a4;
        a4.x = em[i].x * inv; a4.y = em[i].y * inv;
        a4.z = em[i].z * inv; a4.w = em[i].w * inv;
        attnp[idx] = a4;
        float4 n4;
        n4.x = a4.x + c4.x; n4.y = a4.y + c4.y;
        n4.z = a4.z + c4.z; n4.w = a4.w + c4.w;
        covp[idx] = n4;
    }
}

// ============================================================
// Kernel 4: context partials. grid = (NSPLIT, Bx), 256 threads. (R8)
// ============================================================
__global__ void k_context(const float* __restrict__ eo,
                          const float* __restrict__ attn) {
    int b  = blockIdx.y;
    int sp = blockIdx.x;     // 0..NSPLIT-1
    int t  = threadIdx.x;    // 0..255
    int l0 = sp * ROWS_PER_SPLIT;

    __shared__ float sa[ROWS_PER_SPLIT];
    if (t < ROWS_PER_SPLIT) sa[t] = attn[b * Lx + l0 + t];
    __syncthreads();

    const float4* base = (const float4*)eo + ((size_t)b * Lx + l0) * (Dx / 4) + t;
    float4 acc = make_float4(0.f, 0.f, 0.f, 0.f);
#pragma unroll 8
    for (int i = 0; i < ROWS_PER_SPLIT; i++) {
        float a = sa[i];
        float4 v = __ldcs(base + (size_t)i * (Dx / 4));
        acc.x = fmaf(a, v.x, acc.x);
        acc.y = fmaf(a, v.y, acc.y);
        acc.z = fmaf(a, v.z, acc.z);
        acc.w = fmaf(a, v.w, acc.w);
    }
    ((float4*)(g_partial + ((size_t)(b * NSPLIT + sp)) * Dx))[t] = acc;
}

// ============================================================
// Kernel 5: partial reduce, high-occupancy (R12). Deterministic.
// ============================================================
__global__ void k_reduce(float* __restrict__ out) {
    int t = threadIdx.x;
    int o4  = t >> 3;                       // 0..31
    int grp = t & 7;                        // 0..7
    int q = blockIdx.x * 32 + o4;           // global float4 output id
    int b = q >> 8;
    int dq = q & 255;

    const float4* pbase = (const float4*)g_partial + ((size_t)b * NSPLIT) * (Dx / 4) + dq;
    float4 acc = make_float4(0.f, 0.f, 0.f, 0.f);
#pragma unroll
    for (int i = 0; i < 8; i++) {
        float4 p = pbase[(size_t)(grp * 8 + i) * (Dx / 4)];
        acc.x += p.x; acc.y += p.y; acc.z += p.z; acc.w += p.w;
    }

    __shared__ float4 sm[32][8];
    sm[o4][grp] = acc;
    __syncthreads();

    if (grp == 0) {
        float4 sum = sm[o4][0];
#pragma unroll
        for (int g = 1; g < 8; g++) {
            float4 p = sm[o4][g];
            sum.x += p.x; sum.y += p.y; sum.z += p.z; sum.w += p.w;
        }
        ((float4*)(out + CTX_OFF))[q] = sum;
    }
}

// ============================================================
extern "C" void kernel_launch(void* const* d_in, const int* in_sizes, int n_in,
                              void* d_out, int out_size) {
    const float* dec_hidden  = (const float*)d_in[0];
    const float* enc_output  = (const float*)d_in[1];
    const float* enc_feature = (const float*)d_in[2];
    const float* enc_mask    = (const float*)d_in[3];
    // d_in[4] = sec_attn : dead code in reference
    const float* coverage    = (const float*)d_in[5];
    const float* W_feat      = (const float*)d_in[6];
    const float* b_feat      = (const float*)d_in[7];
    const float* w_score     = (const float*)d_in[8];
    const float* w_cov       = (const float*)d_in[9];
    float* out = (float*)d_out;

    k_decfeat<<<dim3(Dx, 2), 256>>>(dec_hidden, W_feat, b_feat);
    k_score  <<<dim3(Lx / SROWS, Bx), 256>>>(enc_feature, coverage, w_score, w_cov);
    k_softmax<<<Bx, 512>>>(enc_mask, coverage, out);
    k_context<<<dim3(NSPLIT, Bx), 256>>>(enc_output, out + ATTN_OFF);
    k_reduce <<<128, 256>>>(out);
}

// round 16
// speedup vs baseline: 1.0193x; 1.0193x over previous
#include <cuda_runtime.h>
#include <cstddef>

#define Bx 16
#define Lx 4096
#define Dx 1024
#define NSPLIT 64
#define ROWS_PER_SPLIT (Lx / NSPLIT)   // 64
#define SROWS 16                       // rows per score block (8 warps x 2)

// ---- scratch (__device__ globals; no allocation allowed) ----
__device__ float g_df[Bx * Dx];               // dec_feature
__device__ float g_score[Bx * Lx];            // pre-softmax scores
__device__ float g_partial[Bx * NSPLIT * Dx]; // context partials

// d_out layout (float32): attn, context, new_coverage
#define ATTN_OFF 0
#define CTX_OFF  (Bx * Lx)
#define COV_OFF  (Bx * Lx + Bx * Dx)

__device__ __forceinline__ float tanh_approx(float x) {
    float y;
    asm("tanh.approx.f32 %0, %1;" : "=f"(y) : "f"(x));
    return y;
}

// ============================================================
// Kernel 1: dec_feature. grid (Dx, 2): block = one d, 8 batches. (R8)
// ============================================================
__global__ void k_decfeat(const float* __restrict__ dh,
                          const float* __restrict__ W,
                          const float* __restrict__ bias) {
    int d  = blockIdx.x;
    int bh = blockIdx.y;               // batch half: b in [8*bh, 8*bh+8)
    int t = threadIdx.x, warp = t >> 5, lane = t & 31;

    float4 w4 = ((const float4*)(W + (size_t)d * Dx))[t];

    float acc[8];
#pragma unroll
    for (int i = 0; i < 8; i++) {
        float4 h4 = ((const float4*)(dh + (size_t)(bh * 8 + i) * Dx))[t];
        acc[i] = w4.x * h4.x + w4.y * h4.y + w4.z * h4.z + w4.w * h4.w;
    }

    bool hi = (lane & 16) != 0;
#pragma unroll
    for (int i = 0; i < 4; i++) {
        float send = hi ? acc[i] : acc[i + 4];
        float r = __shfl_xor_sync(0xffffffffu, send, 16);
        acc[i] = (hi ? acc[i + 4] : acc[i]) + r;
    }
    bool h2 = (lane & 8) != 0;
#pragma unroll
    for (int i = 0; i < 2; i++) {
        float send = h2 ? acc[i] : acc[i + 2];
        float r = __shfl_xor_sync(0xffffffffu, send, 8);
        acc[i] = (h2 ? acc[i + 2] : acc[i]) + r;
    }
    bool h3 = (lane & 4) != 0;
    {
        float send = h3 ? acc[0] : acc[1];
        float r = __shfl_xor_sync(0xffffffffu, send, 4);
        acc[0] = (h3 ? acc[1] : acc[0]) + r;
    }
    acc[0] += __shfl_xor_sync(0xffffffffu, acc[0], 2);
    acc[0] += __shfl_xor_sync(0xffffffffu, acc[0], 1);

    __shared__ float s[8][8];
    if ((lane & 3) == 0) s[warp][(lane >> 2) & 7] = acc[0];
    __syncthreads();
    if (t < 8) {
        float v = 0.f;
#pragma unroll
        for (int w = 0; w < 8; w++) v += s[w][t];
        g_df[(bh * 8 + t) * Dx + d] = v + bias[d];
    }
    cudaTriggerProgrammaticLaunchCompletion();
}

// ============================================================
// Kernel 2: score (R14). PDL: input-only prologue (ws/wc smem fill,
// cov loads) runs BEFORE the dependency sync; g_df read after.
// ============================================================
__global__ void k_score(const float* __restrict__ ef,
                        const float* __restrict__ cov,
                        const float* __restrict__ wscore,
                        const float* __restrict__ wcov) {
    int b  = blockIdx.y;
    int l0 = blockIdx.x * SROWS;
    int t  = threadIdx.x;
    int warp = t >> 5, lane = t & 31;

    int lA = l0 + warp;
    int lB = lA + 8;
    float cA = cov[b * Lx + lA];          // inputs: safe pre-sync
    float cB = cov[b * Lx + lB];
    const float4* rowA = (const float4*)(ef + ((size_t)b * Lx + lA) * Dx);
    const float4* rowB = (const float4*)(ef + ((size_t)b * Lx + lB) * Dx);

    __shared__ float4 s_df[Dx / 4], s_ws[Dx / 4], s_wc[Dx / 4];
    s_ws[t] = ((const float4*)wscore)[t];
    s_wc[t] = ((const float4*)wcov)[t];

    cudaGridDependencySynchronize();      // k_decfeat's g_df now visible
    s_df[t] = ((const float4*)(g_df + (size_t)b * Dx))[t];
    __syncthreads();

    float sumA = 0.f, sumB = 0.f;
#pragma unroll
    for (int j = 0; j < 8; j++) {
        int idx = lane + j * 32;
        float4 eA = __ldcs(&rowA[idx]);
        float4 eB = __ldcs(&rowB[idx]);
        float4 dv = s_df[idx];
        float4 wc = s_wc[idx];
        float4 ws = s_ws[idx];
        sumA += tanh_approx(fmaf(cA, wc.x, eA.x + dv.x)) * ws.x
              + tanh_approx(fmaf(cA, wc.y, eA.y + dv.y)) * ws.y
              + tanh_approx(fmaf(cA, wc.z, eA.z + dv.z)) * ws.z
              + tanh_approx(fmaf(cA, wc.w, eA.w + dv.w)) * ws.w;
        sumB += tanh_approx(fmaf(cB, wc.x, eB.x + dv.x)) * ws.x
              + tanh_approx(fmaf(cB, wc.y, eB.y + dv.y)) * ws.y
              + tanh_approx(fmaf(cB, wc.z, eB.z + dv.z)) * ws.z
              + tanh_approx(fmaf(cB, wc.w, eB.w + dv.w)) * ws.w;
    }
#pragma unroll
    for (int off = 16; off; off >>= 1) {
        sumA += __shfl_down_sync(0xffffffffu, sumA, off);
        sumB += __shfl_down_sync(0xffffffffu, sumB, off);
    }
    if (lane == 0) {
        g_score[b * Lx + lA] = sumA;
        g_score[b * Lx + lB] = sumB;
    }
    cudaTriggerProgrammaticLaunchCompletion();
}

// ============================================================
// Kernel 3: masked softmax (R14, 1024 thr). PDL: mask+cov prefetch
// before sync (inputs), scores after.
// ============================================================
__global__ void k_softmax(const float* __restrict__ mask,
                          const float* __restrict__ cov,
                          float* __restrict__ out) {
    int b = blockIdx.x;
    int t = threadIdx.x;
    __shared__ float red[32];
    __shared__ float bcast;

    float mk[4], cv[4];
#pragma unroll
    for (int i = 0; i < 4; i++) {         // inputs: safe pre-sync
        mk[i] = mask[b * Lx + t + i * 1024];
        cv[i] = cov [b * Lx + t + i * 1024];
    }

    cudaGridDependencySynchronize();      // g_score now visible

    float s[4], em[4];
#pragma unroll
    for (int i = 0; i < 4; i++) s[i] = g_score[b * Lx + t + i * 1024];

    float mx = fmaxf(fmaxf(s[0], s[1]), fmaxf(s[2], s[3]));
#pragma unroll
    for (int off = 16; off; off >>= 1)
        mx = fmaxf(mx, __shfl_xor_sync(0xffffffffu, mx, off));
    if ((t & 31) == 0) red[t >> 5] = mx;
    __syncthreads();
    if (t < 32) {
        float v = red[t];
#pragma unroll
        for (int off = 16; off; off >>= 1)
            v = fmaxf(v, __shfl_xor_sync(0xffffffffu, v, off));
        if (t == 0) bcast = v;
    }
    __syncthreads();
    mx = bcast;

    float lsum = 0.f;
#pragma unroll
    for (int i = 0; i < 4; i++) {
        em[i] = expf(s[i] - mx) * mk[i];
        lsum += em[i];
    }
#pragma unroll
    for (int off = 16; off; off >>= 1)
        lsum += __shfl_xor_sync(0xffffffffu, lsum, off);
    __syncthreads();
    if ((t & 31) == 0) red[t >> 5] = lsum;
    __syncthreads();
    if (t < 32) {
        float v = red[t];
#pragma unroll
        for (int off = 16; off; off >>= 1)
            v += __shfl_xor_sync(0xffffffffu, v, off);
        if (t == 0) bcast = v;
    }
    __syncthreads();
    float inv = 1.f / bcast;

#pragma unroll
    for (int i = 0; i < 4; i++) {
        int idx = b * Lx + t + i * 1024;
        float a = em[i] * inv;
        out[ATTN_OFF + idx] = a;
        out[COV_OFF  + idx] = a + cv[i];
    }
    cudaTriggerProgrammaticLaunchCompletion();
}

// ============================================================
// Kernel 4: context partials (R8). PDL: sync before attn read.
// ============================================================
__global__ void k_context(const float* __restrict__ eo,
                          const float* __restrict__ attn) {
    int b  = blockIdx.y;
    int sp = blockIdx.x;     // 0..NSPLIT-1
    int t  = threadIdx.x;    // 0..255
    int l0 = sp * ROWS_PER_SPLIT;

    const float4* base = (const float4*)eo + ((size_t)b * Lx + l0) * (Dx / 4) + t;

    cudaGridDependencySynchronize();      // attn (in out[]) now visible

    __shared__ float sa[ROWS_PER_SPLIT];
    if (t < ROWS_PER_SPLIT) sa[t] = attn[b * Lx + l0 + t];
    __syncthreads();

    float4 acc = make_float4(0.f, 0.f, 0.f, 0.f);
#pragma unroll 8
    for (int i = 0; i < ROWS_PER_SPLIT; i++) {
        float a = sa[i];
        float4 v = __ldcs(base + (size_t)i * (Dx / 4));
        acc.x = fmaf(a, v.x, acc.x);
        acc.y = fmaf(a, v.y, acc.y);
        acc.z = fmaf(a, v.z, acc.z);
        acc.w = fmaf(a, v.w, acc.w);
    }
    ((float4*)(g_partial + ((size_t)(b * NSPLIT + sp)) * Dx))[t] = acc;
    cudaTriggerProgrammaticLaunchCompletion();
}

// ============================================================
// Kernel 5: partial reduce, high-occupancy (R12). PDL sync first.
// ============================================================
__global__ void k_reduce(float* __restrict__ out) {
    int t = threadIdx.x;
    int o4  = t >> 3;                       // 0..31
    int grp = t & 7;                        // 0..7
    int q = blockIdx.x * 32 + o4;           // global float4 output id
    int b = q >> 8;
    int dq = q & 255;

    cudaGridDependencySynchronize();        // g_partial now visible

    const float4* pbase = (const float4*)g_partial + ((size_t)b * NSPLIT) * (Dx / 4) + dq;
    float4 acc = make_float4(0.f, 0.f, 0.f, 0.f);
#pragma unroll
    for (int i = 0; i < 8; i++) {
        float4 p = pbase[(size_t)(grp * 8 + i) * (Dx / 4)];
        acc.x += p.x; acc.y += p.y; acc.z += p.z; acc.w += p.w;
    }

    __shared__ float4 sm[32][8];
    sm[o4][grp] = acc;
    __syncthreads();

    if (grp == 0) {
        float4 sum = sm[o4][0];
#pragma unroll
        for (int g = 1; g < 8; g++) {
            float4 p = sm[o4][g];
            sum.x += p.x; sum.y += p.y; sum.z += p.z; sum.w += p.w;
        }
        ((float4*)(out + CTX_OFF))[q] = sum;
    }
}

// ============================================================
// Launcher: PDL (programmatic stream serialization) on every
// dependent edge; all launches on the capture (default) stream.
// ============================================================
template <typename K, typename... Args>
static void launch_pdl(dim3 grid, dim3 block, K kernel, Args... args) {
    cudaLaunchConfig_t cfg = {};
    cfg.gridDim = grid;
    cfg.blockDim = block;
    cfg.stream = 0;
    cudaLaunchAttribute a[1];
    a[0].id = cudaLaunchAttributeProgrammaticStreamSerialization;
    a[0].val.programmaticStreamSerializationAllowed = 1;
    cfg.attrs = a;
    cfg.numAttrs = 1;
    cudaLaunchKernelEx(&cfg, kernel, args...);
}

extern "C" void kernel_launch(void* const* d_in, const int* in_sizes, int n_in,
                              void* d_out, int out_size) {
    const float* dec_hidden  = (const float*)d_in[0];
    const float* enc_output  = (const float*)d_in[1];
    const float* enc_feature = (const float*)d_in[2];
    const float* enc_mask    = (const float*)d_in[3];
    // d_in[4] = sec_attn : dead code in reference
    const float* coverage    = (const float*)d_in[5];
    const float* W_feat      = (const float*)d_in[6];
    const float* b_feat      = (const float*)d_in[7];
    const float* w_score     = (const float*)d_in[8];
    const float* w_cov       = (const float*)d_in[9];
    float* out = (float*)d_out;

    k_decfeat<<<dim3(Dx, 2), 256>>>(dec_hidden, W_feat, b_feat);
    launch_pdl(dim3(Lx / SROWS, Bx), dim3(256), k_score,
               enc_feature, coverage, w_score, w_cov);
    launch_pdl(dim3(Bx), dim3(1024), k_softmax, enc_mask, coverage, out);
    launch_pdl(dim3(NSPLIT, Bx), dim3(256), k_context,
               enc_output, (const float*)(out + ATTN_OFF));
    launch_pdl(dim3(128), dim3(256), k_reduce, out);
}